// round 15
// baseline (speedup 1.0000x reference)
#include <cuda_runtime.h>
#include <cuda_bf16.h>
#include <cstdint>
#include <math.h>

// Problem dims
#define BB   256
#define TT   200
#define DD   311
#define UU   256
#define G3   768          // 3*U
#define NOUT 19
#define BT   (BB*TT)      // 51200
#define KPAD 320          // padded K for proj (311 -> 320)

typedef unsigned long long u64;

// ---------------- packed f32x2 helpers (Blackwell PTX) ---------------------
__device__ __forceinline__ void ffma2(u64& d, u64 a, u64 b) {
    asm("fma.rn.f32x2 %0, %1, %2, %0;" : "+l"(d) : "l"(a), "l"(b));
}
__device__ __forceinline__ float lo2(u64 v) {
    return __uint_as_float((unsigned)(v & 0xffffffffull));
}
__device__ __forceinline__ float hi2(u64 v) {
    return __uint_as_float((unsigned)(v >> 32));
}

// ---------------- cp.async / smem helpers ----------------------------------
__device__ __forceinline__ unsigned smem_u32(const void* p) {
    unsigned r;
    asm("{ .reg .u64 t; cvta.to.shared.u64 t, %1; cvt.u32.u64 %0, t; }"
        : "=r"(r) : "l"(p));
    return r;
}
#define CP16(dst, src) \
    asm volatile("cp.async.cg.shared.global [%0], [%1], 16;" :: "r"(dst), "l"(src))
#define CP4(dst, src) \
    asm volatile("cp.async.ca.shared.global [%0], [%1], 4;" :: "r"(dst), "l"(src))
#define CPCOMMIT() asm volatile("cp.async.commit_group;")
#define CPWAIT1()  asm volatile("cp.async.wait_group 1;" ::: "memory")
#define CPWAIT0()  asm volatile("cp.async.wait_group 0;" ::: "memory")

#define NB1() asm volatile("bar.sync 1, 256;" ::: "memory")   // scan team
#define NB2() asm volatile("bar.sync 2, 256;" ::: "memory")   // proj team

// spin until *addr != 0 with gpu-scope acquire (pairs with red.release below)
#define POLL_FLAG(addr) do {                                               \
    int _v;                                                                \
    do {                                                                   \
        asm volatile("ld.acquire.gpu.global.s32 %0, [%1];"                 \
                     : "=r"(_v) : "l"(addr) : "memory");                   \
        if (!_v) __nanosleep(24);                                          \
    } while (!_v);                                                         \
} while (0)

// ---------------- scratch (device globals; no cudaMalloc allowed) ----------
__device__ float g_xp[2][(size_t)BT * G3];    // input projections
__device__ float g_y [2][(size_t)BT * UU];    // hidden sequences
__device__ int   g_mask[BT];
__device__ float g_rkp2[2 * 8 * 96 * 256];    // rk col-major [dir][cc][col][k]
__device__ float g_b1p[2 * 8 * 96];           // recurrent bias per (dir, cc)
__device__ float g_b0p[2 * 8 * 96];           // input bias per (dir, cc)
__device__ float g_kp[2 * 8 * 96 * KPAD];     // k col-major padded [dir][cc][col][k]
__device__ float g_xq[(size_t)BT * KPAD];     // x zero-padded to KPAD
__device__ int   g_flags2[2 * 8 * TT * 8];    // [grp][step][producer cc]

// fast, accurate-enough gate functions (rel err ~2^-21)
__device__ __forceinline__ float fsig(float v) {
    return __fdividef(1.0f, 1.0f + __expf(-v));
}
__device__ __forceinline__ float ftanh(float v) {
    return 1.0f - __fdividef(2.0f, __expf(2.0f * v) + 1.0f);
}

// ---------------- mask: mask[b,t] = any(x[b,t,:] != 0) ---------------------
__global__ __launch_bounds__(256) void mask_kernel(const float* __restrict__ x) {
    int warp = (blockIdx.x * blockDim.x + threadIdx.x) >> 5;
    int lane = threadIdx.x & 31;
    if (warp >= BT) return;
    const float* row = x + (size_t)warp * DD;
    int any = 0;
    for (int i = lane; i < DD; i += 32) any |= (row[i] != 0.0f);
    unsigned b = __ballot_sync(0xffffffffu, any);
    if (lane == 0) g_mask[warp] = (b != 0u);
}

// ---------------- x repack: zero-padded rows of KPAD ------------------------
__global__ __launch_bounds__(256) void xq_kernel(const float* __restrict__ x) {
    int i = blockIdx.x * blockDim.x + threadIdx.x;   // one float4 of g_xq
    if (i >= BT * (KPAD / 4)) return;
    int bt = i / (KPAD / 4), q = i - bt * (KPAD / 4);
    int k = q * 4;
    const float* src = x + (size_t)bt * DD;
    float4 v;
    v.x = (k     < DD) ? src[k]     : 0.0f;
    v.y = (k + 1 < DD) ? src[k + 1] : 0.0f;
    v.z = (k + 2 < DD) ? src[k + 2] : 0.0f;
    v.w = (k + 3 < DD) ? src[k + 3] : 0.0f;
    *(float4*)&g_xq[(size_t)bt * KPAD + k] = v;
}

// ---------------- weight pre-pack ------------------------------------------
// rk: col-major [dir][cc][col96][k256]; k: col-major padded [dir][cc][col96][KPAD]
__global__ __launch_bounds__(256) void pack_kernel(
    const float* __restrict__ rk_f, const float* __restrict__ rk_b,
    const float* __restrict__ b_f,  const float* __restrict__ b_b,
    const float* __restrict__ k_f,  const float* __restrict__ k_b)
{
    int i = blockIdx.x * blockDim.x + threadIdx.x;
    if (i < 2 * 8 * 96 * 256) {
        int k     = i & 255;
        int rest  = i >> 8;
        int c     = rest % 96;
        int slice = rest / 96;
        int cc    = slice & 7;
        int dir   = slice >> 3;
        const float* rk = dir ? rk_b : rk_f;
        g_rkp2[i] = rk[(size_t)k * G3 + (c >> 5) * UU + cc * 32 + (c & 31)];
    }
    if (i < 2 * 8 * 96 * KPAD) {
        int k     = i % KPAD;
        int rest  = i / KPAD;
        int c     = rest % 96;
        int slice = rest / 96;
        int cc    = slice & 7;
        int dir   = slice >> 3;
        const float* kw = dir ? k_b : k_f;
        g_kp[i] = (k < DD)
            ? kw[(size_t)k * G3 + (c >> 5) * UU + cc * 32 + (c & 31)] : 0.0f;
    }
    if (i < 2 * 8 * 96) {
        int c   = i % 96;
        int cc  = (i / 96) & 7;
        int dir = i / (96 * 8);
        const float* b = dir ? b_b : b_f;
        g_b1p[i] = b[G3 + (c >> 5) * UU + cc * 32 + (c & 31)];
        g_b0p[i] = b[     (c >> 5) * UU + cc * 32 + (c & 31)];
    }
}

// ---------------- flag clear (graph replays need fresh flags) --------------
__global__ void clear_flags_kernel() {
    int i = blockIdx.x * blockDim.x + threadIdx.x;
    if (i < 2 * 8 * TT * 8) g_flags2[i] = 0;
}

// ---------------- fused persistent scan + proj producer --------------------
// grid = 128 CTAs, 512 thr, ~213 KB smem -> 1 CTA/SM single wave (<=148).
// blockIdx.x = dir*64 + bg*8 + cc.
// Warps 0-7 (tid<256): R14 chunked scan (bar 1). Warps 8-15: compute this
// CTA's own xp slices [32 b][96 cols] t-by-t in scan order (bar 2), write to
// g_xp, bump smem ready-counter; throttled to <=16 steps ahead of the scan.
// Scan polls the counter before each xp prefetch. Deadlock-free: window>=2,
// proj team has no external dependencies, inter-CTA protocol = R14's flags.
#define KS 260
#define XQS 36           // x chunk row stride (pad vs 32 to break bank wrap)
#define SCF_FLOATS (96*KS + 32*KS + 32*100 + 2*3072 + 96 + 64 \
                    + 2*32*XQS + 2*96*32 + 32*100 + 96 + 8)
#define SCF_BYTES  (SCF_FLOATS * 4)

__global__ __launch_bounds__(512) void scan_fused()
{
    extern __shared__ float sm[];
    float* rs2  = sm;                        // [96][260] rk col-major
    float* hs   = rs2 + 96 * KS;             // [32][260] h
    float* recs = hs + 32 * KS;              // [32][100] rec + b1
    float* xpb  = recs + 32 * 100;           // [2][32][96] xp dbl buffer
    float* b1s  = xpb + 2 * 3072;            // [96]
    int*   mkv  = (int*)(b1s + 96);          // [2][32]
    float* xqb  = (float*)(mkv + 64);        // [2][32][36] x chunks
    float* wqb  = xqb + 2 * 32 * XQS;        // [2][96][32] w chunks
    float* xpo  = wqb + 2 * 96 * 32;         // [32][100] xp staging
    float* b0s  = xpo + 32 * 100;            // [96]
    int*   ctrs = (int*)(b0s + 96);          // [0]=xp slices done, [1]=scan s

    const int tid = threadIdx.x;
    const int cc  = blockIdx.x & 7;
    const int bg  = (blockIdx.x >> 3) & 7;
    const int dir = blockIdx.x >> 6;
    const int u0  = cc * 32;
    const int b0  = bg * 32;

    float*       y   = g_y[dir];
    float*       xpg = g_xp[dir];
    int* flags = g_flags2 + (size_t)(dir * 8 + bg) * TT * 8;
    volatile int* vct = (volatile int*)ctrs;

    const unsigned xpb_a = smem_u32(xpb);
    const unsigned mkv_a = smem_u32(mkv);
    const unsigned hs_a  = smem_u32(hs);
    const unsigned xqb_a = smem_u32(xqb);
    const unsigned wqb_a = smem_u32(wqb);

    // ---- one-time fills (all 512 threads) ----
    if (tid == 0) { ctrs[0] = 0; ctrs[1] = 0; }
    {
        const float4* src =
            (const float4*)(g_rkp2 + (size_t)(dir * 8 + cc) * 96 * 256);
#pragma unroll
        for (int i = 0; i < 12; i++) {
            int idx = tid + 512 * i;         // 6144 quads
            int c = idx >> 6, q = idx & 63;
            *(float4*)&rs2[c * KS + 4 * q] = src[idx];
        }
    }
    if (tid < 96) {
        b1s[tid] = g_b1p[(dir * 8 + cc) * 96 + tid];
        b0s[tid] = g_b0p[(dir * 8 + cc) * 96 + tid];
    }
    for (int i = tid; i < 32 * KS; i += 512) hs[i] = 0.0f;    // h0 = 0
    __syncthreads();                          // only full-CTA sync

    if (tid < 256) {
        // ================= SCAN TEAM (R14 body, bar 1) =================
        auto prefetch = [&](int tn, int buf) {
            unsigned dbase = xpb_a + (unsigned)(buf * 3072) * 4u;
#pragma unroll
            for (int it = 0; it < 3; it++) {
                int j = tid + 256 * it;       // 0..767
                int p = j >> 3, o = j & 7;
                int row = p / 3, seg = p - 3 * row;
                const float* src = xpg +
                    ((size_t)(b0 + row) * TT + tn) * G3 + seg * UU + u0 + o * 4;
                CP16(dbase + (unsigned)(row * 96 + seg * 32 + o * 4) * 4u, src);
            }
            if (tid < 32)
                CP4(mkv_a + (unsigned)(buf * 32 + tid) * 4u,
                    &g_mask[(b0 + tid) * TT + tn]);
        };
        auto load_chunk = [&](int ko, int tp) {
            int rowi = tid >> 3, q = tid & 7;
            const float* src =
                &y[((size_t)(b0 + rowi) * TT + tp) * UU + ko * 32 + q * 4];
            CP16(hs_a + (unsigned)(rowi * KS + ko * 32 + q * 4) * 4u, src);
        };
        const int rt = tid & 15, ct = tid >> 4;
        const int gr = tid >> 3, gu = (tid & 7) * 4;

        auto gemm_chunk = [&](int ko, u64 (&acc)[2][6]) {
            const float* hp0 = &hs[rt * KS + ko * 32];
            const float* hp1 = &hs[(rt + 16) * KS + ko * 32];
            const float* wq  = &rs2[(6 * ct) * KS + ko * 32];
#pragma unroll
            for (int k0 = 0; k0 < 32; k0 += 4) {
                ulonglong2 ha = *(const ulonglong2*)(hp0 + k0);
                ulonglong2 hc = *(const ulonglong2*)(hp1 + k0);
#pragma unroll
                for (int j = 0; j < 6; j++) {
                    ulonglong2 w = *(const ulonglong2*)(wq + j * KS + k0);
                    ffma2(acc[0][j], ha.x, w.x);
                    ffma2(acc[0][j], ha.y, w.y);
                    ffma2(acc[1][j], hc.x, w.x);
                    ffma2(acc[1][j], hc.y, w.y);
                }
            }
        };

        // initial xp prefetch gated on producer
        while (vct[0] < 1) __nanosleep(40);
        asm volatile("" ::: "memory");
        prefetch(dir ? (TT - 1) : 0, 0);
        CPCOMMIT();
        NB1();

        for (int s = 0; s < TT; s++) {
            const int t  = dir ? (TT - 1 - s) : s;
            const int tp = dir ? (t + 1) : (t - 1);
            const int* fprev = flags + (size_t)(s - 1) * 8;

            if (tid == 0) vct[1] = s;          // progress for throttle

            if (s + 1 < TT) {
                while (vct[0] < s + 2) __nanosleep(40);
                asm volatile("" ::: "memory");
                prefetch(dir ? (t - 1) : (t + 1), (s + 1) & 1);
            }
            CPCOMMIT();

            if (s > 0) {
                int k1 = (cc + 1) & 7;
                if (tid == 0) POLL_FLAG(fprev + k1);
                NB1();
                load_chunk(k1, tp);
                CPCOMMIT();
            }

            u64 acc[2][6];
#pragma unroll
            for (int i = 0; i < 2; i++)
#pragma unroll
                for (int j = 0; j < 6; j++) acc[i][j] = 0ull;

            gemm_chunk(cc, acc);

            if (s > 0) {
                for (int j = 1; j < 8; j++) {
                    int kc = (cc + j) & 7;
                    if (j < 7) {
                        int kn = (cc + j + 1) & 7;
                        if (tid == 0) POLL_FLAG(fprev + kn);
                    }
                    NB1();
                    if (j < 7) {
                        int kn = (cc + j + 1) & 7;
                        load_chunk(kn, tp);
                        CPCOMMIT();
                        CPWAIT1();
                    } else {
                        CPWAIT0();
                    }
                    NB1();
                    gemm_chunk(kc, acc);
                }
            } else {
                CPWAIT0();
                NB1();
            }

#pragma unroll
            for (int i = 0; i < 2; i++) {
                int row = rt + 16 * i;
#pragma unroll
                for (int j = 0; j < 6; j++)
                    recs[row * 100 + 6 * ct + j] =
                        lo2(acc[i][j]) + hi2(acc[i][j]) + b1s[6 * ct + j];
            }
            NB1();

            {
                const float* xb = &xpb[(s & 1) * 3072];
                float4 rz = *(float4*)&recs[gr * 100 + gu];
                float4 rr = *(float4*)&recs[gr * 100 + 32 + gu];
                float4 rh = *(float4*)&recs[gr * 100 + 64 + gu];
                float4 xz = *(const float4*)&xb[gr * 96 + gu];
                float4 xr = *(const float4*)&xb[gr * 96 + 32 + gu];
                float4 xh = *(const float4*)&xb[gr * 96 + 64 + gu];
                float4 hp = *(const float4*)&hs[gr * KS + u0 + gu];
                int msk = mkv[(s & 1) * 32 + gr];

                float4 hn;
                {
                    float z0 = fsig(xz.x + rz.x), z1 = fsig(xz.y + rz.y);
                    float z2 = fsig(xz.z + rz.z), z3 = fsig(xz.w + rz.w);
                    float r0 = fsig(xr.x + rr.x), r1 = fsig(xr.y + rr.y);
                    float r2 = fsig(xr.z + rr.z), r3 = fsig(xr.w + rr.w);
                    float h0 = ftanh(xh.x + r0 * rh.x), h1 = ftanh(xh.y + r1 * rh.y);
                    float h2 = ftanh(xh.z + r2 * rh.z), h3 = ftanh(xh.w + r3 * rh.w);
                    hn.x = z0 * hp.x + (1.0f - z0) * h0;
                    hn.y = z1 * hp.y + (1.0f - z1) * h1;
                    hn.z = z2 * hp.z + (1.0f - z2) * h2;
                    hn.w = z3 * hp.w + (1.0f - z3) * h3;
                }
                if (!msk) hn = hp;

                *(float4*)&y[((size_t)(b0 + gr) * TT + t) * UU + u0 + gu] = hn;
                *(float4*)&hs[gr * KS + u0 + gu] = hn;
            }

            NB1();
            if (tid == 0) {
                asm volatile("red.add.release.gpu.global.s32 [%0], 1;"
                             :: "l"(flags + (size_t)s * 8 + cc) : "memory");
            }
        }
    } else {
        // ================= PROJ TEAM (bar 2) =================
        const int pt = tid - 256;             // 0..255
        const int rt2 = pt & 15, ct2 = pt >> 4;
        const int prow = pt >> 3, pq = pt & 7;
        const float* kp = g_kp + (size_t)(dir * 8 + cc) * 96 * KPAD;

        auto ld_x = [&](int t, int k0, int buf) {
            const float* src =
                g_xq + ((size_t)(b0 + prow) * TT + t) * KPAD + k0 + pq * 4;
            CP16(xqb_a + (unsigned)(buf * 32 * XQS + prow * XQS + pq * 4) * 4u, src);
        };
        auto ld_w = [&](int k0, int buf) {
#pragma unroll
            for (int i = 0; i < 3; i++) {
                int idx = pt + 256 * i;       // 768 float4
                int col = idx >> 3, q = idx & 7;
                const float* src = kp + (size_t)col * KPAD + k0 + q * 4;
                CP16(wqb_a + (unsigned)(buf * 3072 + col * 32 + q * 4) * 4u, src);
            }
        };

        for (int s2 = 0; s2 < TT; s2++) {
            const int t = dir ? (TT - 1 - s2) : s2;
            if (pt == 0) {                     // throttle: <=16 ahead
                while (s2 > vct[1] + 16) __nanosleep(100);
            }
            NB2();                             // also protects xpo reuse

            ld_x(t, 0, 0); ld_w(0, 0); CPCOMMIT();

            u64 acc[2][6];
#pragma unroll
            for (int i = 0; i < 2; i++)
#pragma unroll
                for (int j = 0; j < 6; j++) acc[i][j] = 0ull;

            for (int c = 0; c < 10; c++) {     // 10 chunks x 32 k
                if (c + 1 < 10) {
                    ld_x(t, (c + 1) * 32, (c + 1) & 1);
                    ld_w((c + 1) * 32, (c + 1) & 1);
                    CPCOMMIT();
                    CPWAIT1();
                } else {
                    CPWAIT0();
                }
                NB2();
                const float* xb = xqb + (c & 1) * 32 * XQS;
                const float* wb = wqb + (c & 1) * 3072;
                const float* x0 = xb + rt2 * XQS;
                const float* x1 = xb + (rt2 + 16) * XQS;
                const float* wc = wb + (6 * ct2) * 32;
#pragma unroll
                for (int k0 = 0; k0 < 32; k0 += 4) {
                    ulonglong2 xa = *(const ulonglong2*)(x0 + k0);
                    ulonglong2 xc = *(const ulonglong2*)(x1 + k0);
#pragma unroll
                    for (int j = 0; j < 6; j++) {
                        ulonglong2 w = *(const ulonglong2*)(wc + j * 32 + k0);
                        ffma2(acc[0][j], xa.x, w.x);
                        ffma2(acc[0][j], xa.y, w.y);
                        ffma2(acc[1][j], xc.x, w.x);
                        ffma2(acc[1][j], xc.y, w.y);
                    }
                }
                NB2();
            }

            // stage + bias, then coalesced write to g_xp
#pragma unroll
            for (int i = 0; i < 2; i++) {
                int row = rt2 + 16 * i;
#pragma unroll
                for (int j = 0; j < 6; j++)
                    xpo[row * 100 + 6 * ct2 + j] =
                        lo2(acc[i][j]) + hi2(acc[i][j]) + b0s[6 * ct2 + j];
            }
            NB2();
#pragma unroll
            for (int i = 0; i < 3; i++) {
                int idx = pt + 256 * i;        // 768 float4
                int row = idx / 24, q = idx % 24;
                int seg = (q * 4) >> 5, off = q * 4 - seg * 32;
                *(float4*)&xpg[((size_t)(b0 + row) * TT + t) * G3
                               + seg * UU + u0 + off] =
                    *(float4*)&xpo[row * 100 + q * 4];
            }
            NB2();
            if (pt == 0) {
                __threadfence();               // xp visible before counter
                vct[0] = s2 + 1;
            }
        }
    }
}

// ---------------- phase 3: dense + softmax ---------------------------------
__global__ __launch_bounds__(256) void dense_kernel(
    const float* __restrict__ w_d, const float* __restrict__ b_d,
    float* __restrict__ out)
{
    __shared__ float ws[2 * UU * NOUT];
    __shared__ float bs[NOUT];
    for (int i = threadIdx.x; i < 2 * UU * NOUT; i += 256) ws[i] = w_d[i];
    if (threadIdx.x < NOUT) bs[threadIdx.x] = b_d[threadIdx.x];
    __syncthreads();

    int warp = threadIdx.x >> 5, lane = threadIdx.x & 31;
    int row = blockIdx.x * 8 + warp;
    const float* hf = g_y[0] + (size_t)row * UU;
    const float* hb = g_y[1] + (size_t)row * UU;

    float acc[NOUT];
#pragma unroll
    for (int o = 0; o < NOUT; o++) acc[o] = 0.0f;

    for (int j = lane; j < UU; j += 32) {
        float a = hf[j];
        const float* w = &ws[j * NOUT];
#pragma unroll
        for (int o = 0; o < NOUT; o++) acc[o] += a * w[o];
        float b = hb[j];
        const float* w2 = &ws[(UU + j) * NOUT];
#pragma unroll
        for (int o = 0; o < NOUT; o++) acc[o] += b * w2[o];
    }
#pragma unroll
    for (int off = 16; off > 0; off >>= 1)
#pragma unroll
        for (int o = 0; o < NOUT; o++)
            acc[o] += __shfl_xor_sync(0xffffffffu, acc[o], off);

#pragma unroll
    for (int o = 0; o < NOUT; o++) acc[o] += bs[o];
    float m = acc[0];
#pragma unroll
    for (int o = 1; o < NOUT; o++) m = fmaxf(m, acc[o]);
    float sum = 0.0f;
#pragma unroll
    for (int o = 0; o < NOUT; o++) { acc[o] = expf(acc[o] - m); sum += acc[o]; }
    float inv = 1.0f / sum;

    if (lane < NOUT) {
        float v = 0.0f;
#pragma unroll
        for (int o = 0; o < NOUT; o++) if (lane == o) v = acc[o];
        out[(size_t)row * NOUT + lane] = v * inv;
    }
}

// ---------------- launch ----------------------------------------------------
extern "C" void kernel_launch(void* const* d_in, const int* in_sizes, int n_in,
                              void* d_out, int out_size)
{
    const float* x    = (const float*)d_in[0];
    const float* k_f  = (const float*)d_in[1];
    const float* rk_f = (const float*)d_in[2];
    const float* b_f  = (const float*)d_in[3];
    const float* k_b  = (const float*)d_in[4];
    const float* rk_b = (const float*)d_in[5];
    const float* b_b  = (const float*)d_in[6];
    const float* w_d  = (const float*)d_in[7];
    const float* b_d  = (const float*)d_in[8];
    float* out = (float*)d_out;

    mask_kernel<<<BT / 8, 256>>>(x);
    xq_kernel<<<(BT * (KPAD / 4) + 255) / 256, 256>>>(x);
    pack_kernel<<<(2 * 8 * 96 * KPAD + 255) / 256, 256>>>(
        rk_f, rk_b, b_f, b_b, k_f, k_b);
    clear_flags_kernel<<<100, 256>>>();

    // fused persistent scan + proj producer (single wave, 128 CTAs)
    cudaFuncSetAttribute(scan_fused,
                         cudaFuncAttributeMaxDynamicSharedMemorySize,
                         SCF_BYTES);
    scan_fused<<<128, 512, SCF_BYTES>>>();

    dense_kernel<<<BT / 8, 256>>>(w_d, b_d, out);
}

// round 17
// speedup vs baseline: 1.3935x; 1.3935x over previous
#include <cuda_runtime.h>
#include <cuda_bf16.h>
#include <cstdint>
#include <math.h>

// Problem dims
#define BB   256
#define TT   200
#define DD   311
#define UU   256
#define G3   768          // 3*U
#define NOUT 19
#define BT   (BB*TT)      // 51200
#define KP3  960          // 3-term split K (3 x 320)

typedef unsigned long long u64;

// ---------------- packed f32x2 helpers (Blackwell PTX) ---------------------
__device__ __forceinline__ void ffma2(u64& d, u64 a, u64 b) {
    asm("fma.rn.f32x2 %0, %1, %2, %0;" : "+l"(d) : "l"(a), "l"(b));
}
__device__ __forceinline__ float lo2(u64 v) {
    return __uint_as_float((unsigned)(v & 0xffffffffull));
}
__device__ __forceinline__ float hi2(u64 v) {
    return __uint_as_float((unsigned)(v >> 32));
}

// ---------------- cp.async / smem helpers ----------------------------------
__device__ __forceinline__ unsigned smem_u32(const void* p) {
    unsigned r;
    asm("{ .reg .u64 t; cvta.to.shared.u64 t, %1; cvt.u32.u64 %0, t; }"
        : "=r"(r) : "l"(p));
    return r;
}
#define CP16(dst, src) \
    asm volatile("cp.async.cg.shared.global [%0], [%1], 16;" :: "r"(dst), "l"(src))
#define CP4(dst, src) \
    asm volatile("cp.async.ca.shared.global [%0], [%1], 4;" :: "r"(dst), "l"(src))
#define CPCOMMIT() asm volatile("cp.async.commit_group;")
#define CPWAIT1()  asm volatile("cp.async.wait_group 1;" ::: "memory")
#define CPWAIT0()  asm volatile("cp.async.wait_group 0;" ::: "memory")

#define POLL_FLAG(addr) do {                                               \
    int _v;                                                                \
    do {                                                                   \
        asm volatile("ld.acquire.gpu.global.s32 %0, [%1];"                 \
                     : "=r"(_v) : "l"(addr) : "memory");                   \
        if (!_v) __nanosleep(24);                                          \
    } while (!_v);                                                         \
} while (0)

// ---------------- warp-level bf16 MMA (sm_80+ PTX, HMMA pipe) --------------
__device__ __forceinline__ void mma16816(float* c, const unsigned* a,
                                         const unsigned* b) {
    asm volatile(
        "mma.sync.aligned.m16n8k16.row.col.f32.bf16.bf16.f32 "
        "{%0,%1,%2,%3}, {%4,%5,%6,%7}, {%8,%9}, {%0,%1,%2,%3};"
        : "+f"(c[0]), "+f"(c[1]), "+f"(c[2]), "+f"(c[3])
        : "r"(a[0]), "r"(a[1]), "r"(a[2]), "r"(a[3]),
          "r"(b[0]), "r"(b[1]));
}

// ---------------- scratch (device globals; no cudaMalloc allowed) ----------
__device__ float g_xp[2][(size_t)BT * G3];    // input projections
__device__ float g_y [2][(size_t)BT * UU];    // hidden sequences
__device__ int   g_mask[BT];
__device__ float g_rkp2[2 * 8 * 96 * 256];    // rk col-major [dir][cc][col][k]
__device__ float g_b1p[2 * 8 * 96];           // recurrent bias per (dir, cc)
__device__ int   g_flags2[2 * 8 * TT * 8];    // [grp][step][producer cc]
__device__ __nv_bfloat16 g_xa[(size_t)BT * KP3];   // A' = [x1|x1|x2]
__device__ __nv_bfloat16 g_kb[2 * G3 * KP3];       // B' = [k1|k2|k1], [dir][n][k]

__device__ __forceinline__ float fsig(float v) {
    return __fdividef(1.0f, 1.0f + __expf(-v));
}
__device__ __forceinline__ float ftanh(float v) {
    return 1.0f - __fdividef(2.0f, __expf(2.0f * v) + 1.0f);
}

// ---------------- mask: mask[b,t] = any(x[b,t,:] != 0) ---------------------
__global__ __launch_bounds__(256) void mask_kernel(const float* __restrict__ x) {
    int warp = (blockIdx.x * blockDim.x + threadIdx.x) >> 5;
    int lane = threadIdx.x & 31;
    if (warp >= BT) return;
    const float* row = x + (size_t)warp * DD;
    int any = 0;
    for (int i = lane; i < DD; i += 32) any |= (row[i] != 0.0f);
    unsigned b = __ballot_sync(0xffffffffu, any);
    if (lane == 0) g_mask[warp] = (b != 0u);
}

// ---------------- x split: A' rows [x1 | x1 | x2], bf16, zero-padded -------
__global__ __launch_bounds__(256) void xsplit_kernel(const float* __restrict__ x) {
    int i = blockIdx.x * blockDim.x + threadIdx.x;   // BT*40 items, 8 cols each
    if (i >= BT * 40) return;
    int bt = i / 40, g = i - bt * 40;
    int k = g * 8;
    const float* src = x + (size_t)bt * DD;
    unsigned h1[4], h2[4];
#pragma unroll
    for (int j = 0; j < 4; j++) {
        float v0 = (k + 2*j     < DD) ? src[k + 2*j]     : 0.0f;
        float v1 = (k + 2*j + 1 < DD) ? src[k + 2*j + 1] : 0.0f;
        __nv_bfloat16 a0 = __float2bfloat16_rn(v0);
        __nv_bfloat16 a1 = __float2bfloat16_rn(v1);
        __nv_bfloat16 r0 = __float2bfloat16_rn(v0 - __bfloat162float(a0));
        __nv_bfloat16 r1 = __float2bfloat16_rn(v1 - __bfloat162float(a1));
        h1[j] = ((unsigned)__bfloat16_as_ushort(a1) << 16) | __bfloat16_as_ushort(a0);
        h2[j] = ((unsigned)__bfloat16_as_ushort(r1) << 16) | __bfloat16_as_ushort(r0);
    }
    uint4 s1 = make_uint4(h1[0], h1[1], h1[2], h1[3]);
    uint4 s2 = make_uint4(h2[0], h2[1], h2[2], h2[3]);
    __nv_bfloat16* dst = g_xa + (size_t)bt * KP3 + k;
    *(uint4*)(dst)       = s1;
    *(uint4*)(dst + 320) = s1;
    *(uint4*)(dst + 640) = s2;
}

// ---------------- k split/transpose: B'[dir][n][kk] = [k1 | k2 | k1] -------
__global__ __launch_bounds__(256) void kbpack_kernel(
    const float* __restrict__ k_f, const float* __restrict__ k_b)
{
    int i = blockIdx.x * blockDim.x + threadIdx.x;
    if (i >= 2 * G3 * KP3) return;
    int kk  = i % KP3;
    int n   = (i / KP3) % G3;
    int dir = i / (KP3 * G3);
    int sec = kk / 320, kq = kk - sec * 320;
    const float* kw = dir ? k_b : k_f;
    float v = (kq < DD) ? kw[(size_t)kq * G3 + n] : 0.0f;
    __nv_bfloat16 k1 = __float2bfloat16_rn(v);
    __nv_bfloat16 out = (sec == 1)
        ? __float2bfloat16_rn(v - __bfloat162float(k1)) : k1;
    g_kb[i] = out;
}

// ---------------- weight pre-pack (rk for scan) ----------------------------
__global__ __launch_bounds__(256) void pack_kernel(
    const float* __restrict__ rk_f, const float* __restrict__ rk_b,
    const float* __restrict__ b_f,  const float* __restrict__ b_b)
{
    int i = blockIdx.x * blockDim.x + threadIdx.x;
    const int total = 2 * 8 * 96 * 256;
    if (i < total) {
        int k     = i & 255;
        int rest  = i >> 8;
        int c     = rest % 96;
        int slice = rest / 96;
        int cc    = slice & 7;
        int dir   = slice >> 3;
        const float* rk = dir ? rk_b : rk_f;
        g_rkp2[i] = rk[(size_t)k * G3 + (c >> 5) * UU + cc * 32 + (c & 31)];
    }
    if (i < 2 * 8 * 96) {
        int c   = i % 96;
        int cc  = (i / 96) & 7;
        int dir = i / (96 * 8);
        const float* b = dir ? b_b : b_f;
        g_b1p[i] = b[G3 + (c >> 5) * UU + cc * 32 + (c & 31)];
    }
}

__global__ void clear_flags_kernel() {
    int i = blockIdx.x * blockDim.x + threadIdx.x;
    if (i < 2 * 8 * TT * 8) g_flags2[i] = 0;
}

// ---------------- phase 1: bf16 warp-MMA proj GEMM -------------------------
// grid (6, 400, 2): n-tile 128, m-tile 128, dir. 256 thr = 8 warps (4m x 2n),
// warp tile 32x64, K' = 960 in 15 chunks of 64, cp.async double buffer.
// 3-term split: xp = x1*k1 + x1*k2 + x2*k1 (fp32 accum) -> ~1e-5 rel err.
#define SA 72                          // smem row stride (bf16), 144 B
#define PJ_BUF (128 * SA)              // elements per buffer
#define PJ_SMEM (4 * PJ_BUF * 2)       // bytes: A0,A1,B0,B1

__global__ __launch_bounds__(256) void proj_hmma_kernel(
    const float* __restrict__ b_f, const float* __restrict__ b_b)
{
    extern __shared__ __nv_bfloat16 smb[];
    const unsigned sb = smem_u32(smb);

    const int tid  = threadIdx.x;
    const int warp = tid >> 5, lane = tid & 31;
    const int wm = warp & 3, wn = warp >> 2;     // 4 x 2 warp grid
    const int rg = lane >> 2;                    // 0..7
    const int q2 = (lane & 3) * 2;               // 0,2,4,6

    const int n0  = blockIdx.x * 128;
    const int m0  = blockIdx.y * 128;
    const int dir = blockIdx.z;
    const float* bias = dir ? b_b : b_f;         // row 0 = input bias
    float* xp = g_xp[dir];

    // smem element offsets
    const int A0 = 0, B0 = 2 * PJ_BUF;

    // load one 64-k chunk of A (128 rows) + B (128 rows) into buffer buf
    auto load_chunk = [&](int c, int buf) {
        int k0 = c * 64;
        unsigned abase = sb + (unsigned)(A0 + buf * PJ_BUF) * 2u;
        unsigned bbase = sb + (unsigned)(B0 + buf * PJ_BUF) * 2u;
#pragma unroll
        for (int i = 0; i < 4; i++) {
            int idx = tid + 256 * i;             // 1024
            int row = idx >> 3, seg = idx & 7;
            CP16(abase + (unsigned)(row * 144 + seg * 16),
                 g_xa + (size_t)(m0 + row) * KP3 + k0 + seg * 8);
        }
#pragma unroll
        for (int i = 0; i < 4; i++) {
            int idx = tid + 256 * i;
            int row = idx >> 3, seg = idx & 7;
            CP16(bbase + (unsigned)(row * 144 + seg * 16),
                 g_kb + ((size_t)dir * G3 + n0 + row) * KP3 + k0 + seg * 8);
        }
    };

    float c[2][8][4];
#pragma unroll
    for (int mf = 0; mf < 2; mf++)
#pragma unroll
        for (int nf = 0; nf < 8; nf++)
#pragma unroll
            for (int j = 0; j < 4; j++) c[mf][nf][j] = 0.0f;

    load_chunk(0, 0);
    CPCOMMIT();

    for (int ch = 0; ch < 15; ch++) {
        const int buf = ch & 1;
        if (ch + 1 < 15) { load_chunk(ch + 1, buf ^ 1); CPCOMMIT(); CPWAIT1(); }
        else             { CPWAIT0(); }
        __syncthreads();

        const __nv_bfloat16* As = smb + A0 + buf * PJ_BUF;
        const __nv_bfloat16* Bs = smb + B0 + buf * PJ_BUF;

#pragma unroll
        for (int kk = 0; kk < 64; kk += 16) {
            unsigned a[2][4];
#pragma unroll
            for (int mf = 0; mf < 2; mf++) {
                int r0 = wm * 32 + mf * 16 + rg;
                a[mf][0] = *(const unsigned*)&As[r0 * SA + kk + q2];
                a[mf][1] = *(const unsigned*)&As[(r0 + 8) * SA + kk + q2];
                a[mf][2] = *(const unsigned*)&As[r0 * SA + kk + 8 + q2];
                a[mf][3] = *(const unsigned*)&As[(r0 + 8) * SA + kk + 8 + q2];
            }
            unsigned b[8][2];
#pragma unroll
            for (int nf = 0; nf < 8; nf++) {
                int n = wn * 64 + nf * 8 + rg;
                b[nf][0] = *(const unsigned*)&Bs[n * SA + kk + q2];
                b[nf][1] = *(const unsigned*)&Bs[n * SA + kk + 8 + q2];
            }
#pragma unroll
            for (int mf = 0; mf < 2; mf++)
#pragma unroll
                for (int nf = 0; nf < 8; nf++)
                    mma16816(c[mf][nf], a[mf], b[nf]);
        }
        __syncthreads();
    }

    // epilogue: C fragment (row = lane/4 (+8), col = 2*(lane%4)) + bias
#pragma unroll
    for (int mf = 0; mf < 2; mf++) {
        int row = m0 + wm * 32 + mf * 16 + rg;
#pragma unroll
        for (int nf = 0; nf < 8; nf++) {
            int col = n0 + wn * 64 + nf * 8 + q2;
            float b0v = __ldg(&bias[col]), b1v = __ldg(&bias[col + 1]);
            float2 v0 = make_float2(c[mf][nf][0] + b0v, c[mf][nf][1] + b1v);
            float2 v1 = make_float2(c[mf][nf][2] + b0v, c[mf][nf][3] + b1v);
            *(float2*)&xp[(size_t)row * G3 + col] = v0;
            *(float2*)&xp[(size_t)(row + 8) * G3 + col] = v1;
        }
    }
}

// ---------------- phase 2: persistent scan, chunked k-pipeline (R14) -------
#define KS 260
#define SC2_FLOATS (96 * KS + 32 * KS + 32 * 100 + 2 * 3072 + 96 + 64)
#define SC2_BYTES  (SC2_FLOATS * 4)

__global__ __launch_bounds__(256) void scan_chunked()
{
    extern __shared__ float sm[];
    float* rs2  = sm;                       // [96][260] rk slice, col-major
    float* hs   = rs2 + 96 * KS;            // [32][260] h (full 256 units)
    float* recs = hs + 32 * KS;             // [32][100] rec + b1
    float* xpb  = recs + 32 * 100;          // [2][32][96] xp double buffer
    float* b1s  = xpb + 2 * 3072;           // [96]
    int*   mkv  = (int*)(b1s + 96);         // [2][32]

    const int tid = threadIdx.x;
    const int cc  = blockIdx.x & 7;
    const int bg  = (blockIdx.x >> 3) & 7;
    const int dir = blockIdx.x >> 6;
    const int u0  = cc * 32;
    const int b0  = bg * 32;

    float*       y  = g_y[dir];
    const float* xp = g_xp[dir];
    int* flags = g_flags2 + (size_t)(dir * 8 + bg) * TT * 8;

    const unsigned xpb_a = smem_u32(xpb);
    const unsigned mkv_a = smem_u32(mkv);
    const unsigned hs_a  = smem_u32(hs);

    {
        const float4* src =
            (const float4*)(g_rkp2 + (size_t)(dir * 8 + cc) * 96 * 256);
#pragma unroll
        for (int i = 0; i < 24; i++) {
            int idx = tid + 256 * i;
            int c = idx >> 6, q = idx & 63;
            *(float4*)&rs2[c * KS + 4 * q] = src[idx];
        }
    }
    if (tid < 96) b1s[tid] = g_b1p[(dir * 8 + cc) * 96 + tid];
    for (int i = tid; i < 32 * KS; i += 256) hs[i] = 0.0f;

    auto prefetch = [&](int tn, int buf) {
        unsigned dbase = xpb_a + (unsigned)(buf * 3072) * 4u;
#pragma unroll
        for (int it = 0; it < 3; it++) {
            int j = tid + 256 * it;
            int p = j >> 3, o = j & 7;
            int row = p / 3, seg = p - 3 * row;
            const float* src =
                xp + ((size_t)(b0 + row) * TT + tn) * G3 + seg * UU + u0 + o * 4;
            CP16(dbase + (unsigned)(row * 96 + seg * 32 + o * 4) * 4u, src);
        }
        if (tid < 32)
            CP4(mkv_a + (unsigned)(buf * 32 + tid) * 4u,
                &g_mask[(b0 + tid) * TT + tn]);
    };
    auto load_chunk = [&](int ko, int tp) {
        int rowi = tid >> 3, q = tid & 7;
        const float* src =
            &y[((size_t)(b0 + rowi) * TT + tp) * UU + ko * 32 + q * 4];
        CP16(hs_a + (unsigned)(rowi * KS + ko * 32 + q * 4) * 4u, src);
    };

    const int rt = tid & 15, ct = tid >> 4;
    const int gr = tid >> 3, gu = (tid & 7) * 4;

    auto gemm_chunk = [&](int ko, u64 (&acc)[2][6]) {
        const float* hp0 = &hs[rt * KS + ko * 32];
        const float* hp1 = &hs[(rt + 16) * KS + ko * 32];
        const float* wq  = &rs2[(6 * ct) * KS + ko * 32];
#pragma unroll
        for (int k0 = 0; k0 < 32; k0 += 4) {
            ulonglong2 ha = *(const ulonglong2*)(hp0 + k0);
            ulonglong2 hc = *(const ulonglong2*)(hp1 + k0);
#pragma unroll
            for (int j = 0; j < 6; j++) {
                ulonglong2 w = *(const ulonglong2*)(wq + j * KS + k0);
                ffma2(acc[0][j], ha.x, w.x);
                ffma2(acc[0][j], ha.y, w.y);
                ffma2(acc[1][j], hc.x, w.x);
                ffma2(acc[1][j], hc.y, w.y);
            }
        }
    };

    prefetch(dir ? (TT - 1) : 0, 0);
    CPCOMMIT();
    __syncthreads();

    for (int s = 0; s < TT; s++) {
        const int t  = dir ? (TT - 1 - s) : s;
        const int tp = dir ? (t + 1) : (t - 1);
        const int* fprev = flags + (size_t)(s - 1) * 8;

        if (s + 1 < TT) prefetch(dir ? (t - 1) : (t + 1), (s + 1) & 1);
        CPCOMMIT();

        if (s > 0) {
            int k1 = (cc + 1) & 7;
            if (tid == 0) POLL_FLAG(fprev + k1);
            __syncthreads();
            load_chunk(k1, tp);
            CPCOMMIT();
        }

        u64 acc[2][6];
#pragma unroll
        for (int i = 0; i < 2; i++)
#pragma unroll
            for (int j = 0; j < 6; j++) acc[i][j] = 0ull;

        gemm_chunk(cc, acc);

        if (s > 0) {
            for (int j = 1; j < 8; j++) {
                int kc = (cc + j) & 7;
                if (j < 7) {
                    int kn = (cc + j + 1) & 7;
                    if (tid == 0) POLL_FLAG(fprev + kn);
                }
                __syncthreads();
                if (j < 7) {
                    int kn = (cc + j + 1) & 7;
                    load_chunk(kn, tp);
                    CPCOMMIT();
                    CPWAIT1();
                } else {
                    CPWAIT0();
                }
                __syncthreads();
                gemm_chunk(kc, acc);
            }
        } else {
            CPWAIT0();
            __syncthreads();
        }

#pragma unroll
        for (int i = 0; i < 2; i++) {
            int row = rt + 16 * i;
#pragma unroll
            for (int j = 0; j < 6; j++)
                recs[row * 100 + 6 * ct + j] =
                    lo2(acc[i][j]) + hi2(acc[i][j]) + b1s[6 * ct + j];
        }
        __syncthreads();

        {
            const float* xb = &xpb[(s & 1) * 3072];
            float4 rz = *(float4*)&recs[gr * 100 + gu];
            float4 rr = *(float4*)&recs[gr * 100 + 32 + gu];
            float4 rh = *(float4*)&recs[gr * 100 + 64 + gu];
            float4 xz = *(const float4*)&xb[gr * 96 + gu];
            float4 xr = *(const float4*)&xb[gr * 96 + 32 + gu];
            float4 xh = *(const float4*)&xb[gr * 96 + 64 + gu];
            float4 hp = *(const float4*)&hs[gr * KS + u0 + gu];
            int msk = mkv[(s & 1) * 32 + gr];

            float4 hn;
            {
                float z0 = fsig(xz.x + rz.x), z1 = fsig(xz.y + rz.y);
                float z2 = fsig(xz.z + rz.z), z3 = fsig(xz.w + rz.w);
                float r0 = fsig(xr.x + rr.x), r1 = fsig(xr.y + rr.y);
                float r2 = fsig(xr.z + rr.z), r3 = fsig(xr.w + rr.w);
                float h0 = ftanh(xh.x + r0 * rh.x), h1 = ftanh(xh.y + r1 * rh.y);
                float h2 = ftanh(xh.z + r2 * rh.z), h3 = ftanh(xh.w + r3 * rh.w);
                hn.x = z0 * hp.x + (1.0f - z0) * h0;
                hn.y = z1 * hp.y + (1.0f - z1) * h1;
                hn.z = z2 * hp.z + (1.0f - z2) * h2;
                hn.w = z3 * hp.w + (1.0f - z3) * h3;
            }
            if (!msk) hn = hp;

            *(float4*)&y[((size_t)(b0 + gr) * TT + t) * UU + u0 + gu] = hn;
            *(float4*)&hs[gr * KS + u0 + gu] = hn;
        }

        __syncthreads();
        if (tid == 0) {
            asm volatile("red.add.release.gpu.global.s32 [%0], 1;"
                         :: "l"(flags + (size_t)s * 8 + cc) : "memory");
        }
    }
}

// ---------------- phase 3: dense + softmax ---------------------------------
__global__ __launch_bounds__(256) void dense_kernel(
    const float* __restrict__ w_d, const float* __restrict__ b_d,
    float* __restrict__ out)
{
    __shared__ float ws[2 * UU * NOUT];
    __shared__ float bs[NOUT];
    for (int i = threadIdx.x; i < 2 * UU * NOUT; i += 256) ws[i] = w_d[i];
    if (threadIdx.x < NOUT) bs[threadIdx.x] = b_d[threadIdx.x];
    __syncthreads();

    int warp = threadIdx.x >> 5, lane = threadIdx.x & 31;
    int row = blockIdx.x * 8 + warp;
    const float* hf = g_y[0] + (size_t)row * UU;
    const float* hb = g_y[1] + (size_t)row * UU;

    float acc[NOUT];
#pragma unroll
    for (int o = 0; o < NOUT; o++) acc[o] = 0.0f;

    for (int j = lane; j < UU; j += 32) {
        float a = hf[j];
        const float* w = &ws[j * NOUT];
#pragma unroll
        for (int o = 0; o < NOUT; o++) acc[o] += a * w[o];
        float b = hb[j];
        const float* w2 = &ws[(UU + j) * NOUT];
#pragma unroll
        for (int o = 0; o < NOUT; o++) acc[o] += b * w2[o];
    }
#pragma unroll
    for (int off = 16; off > 0; off >>= 1)
#pragma unroll
        for (int o = 0; o < NOUT; o++)
            acc[o] += __shfl_xor_sync(0xffffffffu, acc[o], off);

#pragma unroll
    for (int o = 0; o < NOUT; o++) acc[o] += bs[o];
    float m = acc[0];
#pragma unroll
    for (int o = 1; o < NOUT; o++) m = fmaxf(m, acc[o]);
    float sum = 0.0f;
#pragma unroll
    for (int o = 0; o < NOUT; o++) { acc[o] = expf(acc[o] - m); sum += acc[o]; }
    float inv = 1.0f / sum;

    if (lane < NOUT) {
        float v = 0.0f;
#pragma unroll
        for (int o = 0; o < NOUT; o++) if (lane == o) v = acc[o];
        out[(size_t)row * NOUT + lane] = v * inv;
    }
}

// ---------------- launch ----------------------------------------------------
extern "C" void kernel_launch(void* const* d_in, const int* in_sizes, int n_in,
                              void* d_out, int out_size)
{
    const float* x    = (const float*)d_in[0];
    const float* k_f  = (const float*)d_in[1];
    const float* rk_f = (const float*)d_in[2];
    const float* b_f  = (const float*)d_in[3];
    const float* k_b  = (const float*)d_in[4];
    const float* rk_b = (const float*)d_in[5];
    const float* b_b  = (const float*)d_in[6];
    const float* w_d  = (const float*)d_in[7];
    const float* b_d  = (const float*)d_in[8];
    float* out = (float*)d_out;

    mask_kernel<<<BT / 8, 256>>>(x);
    xsplit_kernel<<<(BT * 40 + 255) / 256, 256>>>(x);
    kbpack_kernel<<<(2 * G3 * KP3 + 255) / 256, 256>>>(k_f, k_b);
    pack_kernel<<<(2 * 8 * 96 * 256) / 256, 256>>>(rk_f, rk_b, b_f, b_b);
    clear_flags_kernel<<<100, 256>>>();

    // bf16 warp-MMA 3-term-split proj GEMM (HMMA pipe; tcgen05 unavailable
    // at the harness's sm_100 PTX target)
    cudaFuncSetAttribute(proj_hmma_kernel,
                         cudaFuncAttributeMaxDynamicSharedMemorySize, PJ_SMEM);
    dim3 pg(G3 / 128, BT / 128, 2);
    proj_hmma_kernel<<<pg, 256, PJ_SMEM>>>(b_f, b_b);

    // persistent chunked scan (R14, proven)
    cudaFuncSetAttribute(scan_chunked,
                         cudaFuncAttributeMaxDynamicSharedMemorySize, SC2_BYTES);
    scan_chunked<<<128, 256, SC2_BYTES>>>();

    dense_kernel<<<BT / 8, 256>>>(w_d, b_d, out);
}